// round 2
// baseline (speedup 1.0000x reference)
#include <cuda_runtime.h>
#include <cstdint>
#include <cstddef>

// Problem constants
static constexpr int B = 8192;
static constexpr int S = 256;
static constexpr int R = 8192;

// 256 MB flux scratch (device global: the sanctioned scratch mechanism)
__device__ float g_flux[(size_t)B * (size_t)R];

// =====================================================================
// Helpers (all sm_80-baseline PTX; nothing sm_103a-gated)
// =====================================================================
__device__ __forceinline__ uint32_t smem_u32(const void* p) {
    uint32_t a;
    asm("{ .reg .u64 t; cvta.to.shared.u64 t, %1; cvt.u32.u64 %0, t; }"
        : "=r"(a) : "l"(p));
    return a;
}

__device__ __forceinline__ void cp_async16(uint32_t s, const void* g) {
    asm volatile("cp.async.cg.shared.global [%0], [%1], 16;"
                 :: "r"(s), "l"(g) : "memory");
}
__device__ __forceinline__ void cp_commit() {
    asm volatile("cp.async.commit_group;" ::: "memory");
}
__device__ __forceinline__ void cp_wait1() {
    asm volatile("cp.async.wait_group 1;" ::: "memory");
}

// SW128 swizzle: XOR byte-addr bits [6:4] with bits [9:7]
__device__ __forceinline__ uint32_t swz128(uint32_t off) {
    return off ^ ((off >> 3) & 0x70);
}

// Load fp32 from smem and round to tf32 (rna) for mma input
__device__ __forceinline__ uint32_t ld_tf32(uint32_t addr) {
    float v;
    asm volatile("ld.shared.f32 %0, [%1];" : "=f"(v) : "r"(addr));
    uint32_t t;
    asm("cvt.rna.tf32.f32 %0, %1;" : "=r"(t) : "f"(v));
    return t;
}

// m16n8k8 tf32 mma, C += A*B
__device__ __forceinline__ void mma_m16n8k8(float* c, const uint32_t* a,
                                            const uint32_t* b) {
    asm volatile(
        "mma.sync.aligned.m16n8k8.row.col.f32.tf32.tf32.f32 "
        "{%0,%1,%2,%3}, {%4,%5,%6,%7}, {%8,%9}, {%0,%1,%2,%3};"
        : "+f"(c[0]), "+f"(c[1]), "+f"(c[2]), "+f"(c[3])
        : "r"(a[0]), "r"(a[1]), "r"(a[2]), "r"(a[3]),
          "r"(b[0]), "r"(b[1]));
}

// =====================================================================
// Pass 1: flux[b,r] = rate(b,r) * ab_pad[b,i0]*ab_pad[b,i1]
// =====================================================================
static constexpr int BT = 16;  // b-rows per block (amortizes per-r param loads 16x)

__global__ void __launch_bounds__(256) flux_kernel(
    const float* __restrict__ ab, const float* __restrict__ temp,
    const float* __restrict__ cr, const float* __restrict__ fuv,
    const float* __restrict__ alpha, const float* __restrict__ beta,
    const float* __restrict__ gamma, const int* __restrict__ rm2,
    const int* __restrict__ rtype)
{
    __shared__ float s_ab[BT][S + 1];
    __shared__ float sL[BT], sInvT[BT], sCr[BT], sFuv[BT];

    const int b0 = blockIdx.x * BT;
    const int tid = threadIdx.x;

    for (int i = tid; i < BT * S; i += 256) {
        int bi = i >> 8, si = i & 255;
        s_ab[bi][si] = ab[(size_t)(b0 + bi) * S + si];
    }
    if (tid < BT) {
        s_ab[tid][S] = 1.0f;  // ab_pad ones column (index == S)
        float T = temp[b0 + tid];
        sL[tid] = __logf(T * (1.0f / 300.0f));
        sInvT[tid] = 1.0f / T;
        sCr[tid] = cr[b0 + tid];
        sFuv[tid] = fuv[b0 + tid];
    }
    __syncthreads();

    for (int r = tid; r < R; r += 256) {
        const float a = alpha[r];
        const float be = beta[r];
        const float ga = gamma[r];
        const int rt = rtype[r];
        const int i0 = rm2[2 * r];
        const int i1 = rm2[2 * r + 1];
        const float efuv = a * __expf(-ga);  // b-independent part of k_fuv
        float* fout = g_flux + (size_t)b0 * R + r;
#pragma unroll
        for (int bi = 0; bi < BT; bi++) {
            float k;
            if (rt == 0)      k = a * __expf(be * sL[bi] - ga * sInvT[bi]);
            else if (rt == 1) k = a * sCr[bi];
            else              k = efuv * sFuv[bi];
            fout[(size_t)bi * R] = k * s_ab[bi][i0] * s_ab[bi][i1];
        }
    }
}

// =====================================================================
// Pass 2: out[b,s] = sum_r flux[b,r] * inc[s,r]
// mma.sync tf32 GEMM. CTA tile M=64 x N=256(full S) x K=32.
// 8 warps, warp tile 32x64. 3-stage cp.async pipeline, SW128 swizzle.
// =====================================================================
static constexpr int TM = 64, TN = 256, TK = 32;
static constexpr int NSTAGE = 3;
static constexpr int NK = R / TK;                 // 256
static constexpr int A_BYTES = TM * TK * 4;       // 8192 (multiple of 1024: swizzle-safe base)
static constexpr int STAGE_B = (TM + TN) * TK * 4;  // 40960
static constexpr int SMEM_TOTAL = NSTAGE * STAGE_B; // 122880

__global__ void __launch_bounds__(256) gemm_kernel(
    const float* __restrict__ inc, float* __restrict__ out)
{
    extern __shared__ char smem[];
    const uint32_t sb = smem_u32(smem);
    const int tid = threadIdx.x;
    const int wid = tid >> 5;
    const int lane = tid & 31;
    const int lr = lane >> 2;   // fragment "group" row
    const int lc = lane & 3;    // fragment k sub-index
    const int m0 = blockIdx.x * TM;
    const int warp_m = wid & 1;   // 2 warps over M (32 rows each)
    const int warp_n = wid >> 1;  // 4 warps over N (64 cols each)

    auto load_stage = [&](int buf, int ks) {
        const uint32_t base = sb + buf * STAGE_B;
        const size_t k0 = (size_t)ks * TK;
        // A tile: 64 rows x 128B (2 chunks/thread)
#pragma unroll
        for (int idx = tid; idx < TM * 8; idx += 256) {
            int row = idx >> 3, j = idx & 7;
            cp_async16(base + swz128((uint32_t)(row * 128 + j * 16)),
                       g_flux + (size_t)(m0 + row) * R + k0 + j * 4);
        }
        // B tile: 256 rows x 128B (8 chunks/thread)
        const uint32_t bbase = base + A_BYTES;
#pragma unroll
        for (int idx = tid; idx < TN * 8; idx += 256) {
            int row = idx >> 3, j = idx & 7;
            cp_async16(bbase + swz128((uint32_t)(row * 128 + j * 16)),
                       inc + (size_t)row * R + k0 + j * 4);
        }
    };

    float c[2][8][4];
#pragma unroll
    for (int i = 0; i < 2; i++)
#pragma unroll
        for (int j = 0; j < 8; j++)
#pragma unroll
            for (int q = 0; q < 4; q++) c[i][j][q] = 0.0f;

    // Prologue: 2 stages in flight
    load_stage(0, 0); cp_commit();
    load_stage(1, 1); cp_commit();

    for (int k = 0; k < NK; k++) {
        cp_wait1();          // stage k complete (<=1 group still pending)
        __syncthreads();     // also guards reuse of buffer (k+2)%3 from iter k-1

        const int t = k + 2;
        if (t < NK) load_stage(t % 3, t);
        cp_commit();         // empty group when no loads: keeps group count uniform

        const uint32_t abase = sb + (k % 3) * STAGE_B;
        const uint32_t bbase = abase + A_BYTES;

#pragma unroll
        for (int ks = 0; ks < 4; ks++) {  // 4 x k8 steps cover TK=32
            uint32_t a[2][4];
#pragma unroll
            for (int i = 0; i < 2; i++) {
                const int row = warp_m * 32 + i * 16 + lr;
                const int col = ks * 8 + lc;
                a[i][0] = ld_tf32(abase + swz128((uint32_t)(row * 128 + col * 4)));
                a[i][1] = ld_tf32(abase + swz128((uint32_t)((row + 8) * 128 + col * 4)));
                a[i][2] = ld_tf32(abase + swz128((uint32_t)(row * 128 + (col + 4) * 4)));
                a[i][3] = ld_tf32(abase + swz128((uint32_t)((row + 8) * 128 + (col + 4) * 4)));
            }
            uint32_t b[8][2];
#pragma unroll
            for (int j = 0; j < 8; j++) {
                const int nrow = warp_n * 64 + j * 8 + lr;  // n index
                const int kcol = ks * 8 + lc;               // k index
                b[j][0] = ld_tf32(bbase + swz128((uint32_t)(nrow * 128 + kcol * 4)));
                b[j][1] = ld_tf32(bbase + swz128((uint32_t)(nrow * 128 + (kcol + 4) * 4)));
            }
#pragma unroll
            for (int i = 0; i < 2; i++)
#pragma unroll
                for (int j = 0; j < 8; j++)
                    mma_m16n8k8(c[i][j], a[i], b[j]);
        }
    }

    // Epilogue: write C fragments (covers the full 64x256 tile exactly)
#pragma unroll
    for (int i = 0; i < 2; i++) {
#pragma unroll
        for (int j = 0; j < 8; j++) {
            const int row = m0 + warp_m * 32 + i * 16 + lr;
            const int col = warp_n * 64 + j * 8 + 2 * lc;
            float2 v0; v0.x = c[i][j][0]; v0.y = c[i][j][1];
            float2 v1; v1.x = c[i][j][2]; v1.y = c[i][j][3];
            *reinterpret_cast<float2*>(out + (size_t)row * S + col) = v0;
            *reinterpret_cast<float2*>(out + (size_t)(row + 8) * S + col) = v1;
        }
    }
}

// =====================================================================
// Launch
// =====================================================================
extern "C" void kernel_launch(void* const* d_in, const int* in_sizes, int n_in,
                              void* d_out, int out_size) {
    // metadata order: time, abundances, temperature, cr_rate, fuv_rate,
    //                 incidence, alpha, beta, gamma, reactant_multipliers, rtype
    const float* ab    = (const float*)d_in[1];
    const float* temp  = (const float*)d_in[2];
    const float* cr    = (const float*)d_in[3];
    const float* fuv   = (const float*)d_in[4];
    const float* inc   = (const float*)d_in[5];
    const float* alpha = (const float*)d_in[6];
    const float* beta  = (const float*)d_in[7];
    const float* gamma = (const float*)d_in[8];
    const int*   rm    = (const int*)d_in[9];
    const int*   rtype = (const int*)d_in[10];
    float* out = (float*)d_out;

    static bool attr_set = false;
    if (!attr_set) {
        cudaFuncSetAttribute(gemm_kernel,
                             cudaFuncAttributeMaxDynamicSharedMemorySize, SMEM_TOTAL);
        attr_set = true;
    }

    flux_kernel<<<B / BT, 256>>>(ab, temp, cr, fuv, alpha, beta, gamma, rm, rtype);
    gemm_kernel<<<B / TM, 256, SMEM_TOTAL>>>(inc, out);
}

// round 4
// speedup vs baseline: 1.2859x; 1.2859x over previous
#include <cuda_runtime.h>
#include <cstdint>
#include <cstddef>

// Problem constants
static constexpr int B = 8192;
static constexpr int S = 256;
static constexpr int R = 8192;

// 8 MB scratch: inc pre-converted to tf32 bit patterns (device global = sanctioned scratch)
__device__ uint32_t g_incT[(size_t)S * (size_t)R];

// =====================================================================
// Helpers (sm_80-baseline PTX only; nothing sm_103a-gated)
// =====================================================================
__device__ __forceinline__ uint32_t smem_u32(const void* p) {
    uint32_t a;
    asm("{ .reg .u64 t; cvta.to.shared.u64 t, %1; cvt.u32.u64 %0, t; }"
        : "=r"(a) : "l"(p));
    return a;
}
__device__ __forceinline__ void cp_async16(uint32_t s, const void* g) {
    asm volatile("cp.async.cg.shared.global [%0], [%1], 16;"
                 :: "r"(s), "l"(g) : "memory");
}
__device__ __forceinline__ void cp_commit() {
    asm volatile("cp.async.commit_group;" ::: "memory");
}
__device__ __forceinline__ void cp_wait1() {
    asm volatile("cp.async.wait_group 1;" ::: "memory");
}
// SW128 swizzle: XOR byte-addr bits [6:4] with bits [9:7]
__device__ __forceinline__ uint32_t swz128(uint32_t off) {
    return off ^ ((off >> 3) & 0x70);
}
__device__ __forceinline__ uint32_t f2tf32(float f) {
    uint32_t t;
    asm("cvt.rna.tf32.f32 %0, %1;" : "=r"(t) : "f"(f));
    return t;
}
__device__ __forceinline__ void ldsm_x4(uint32_t* r, uint32_t addr) {
    asm volatile("ldmatrix.sync.aligned.m8n8.x4.shared.b16 {%0,%1,%2,%3}, [%4];"
                 : "=r"(r[0]), "=r"(r[1]), "=r"(r[2]), "=r"(r[3]) : "r"(addr));
}
__device__ __forceinline__ void sts128(uint32_t addr, uint32_t v0, uint32_t v1,
                                       uint32_t v2, uint32_t v3) {
    asm volatile("st.shared.v4.b32 [%0], {%1,%2,%3,%4};"
                 :: "r"(addr), "r"(v0), "r"(v1), "r"(v2), "r"(v3) : "memory");
}
__device__ __forceinline__ void mma_m16n8k8(float* c, const uint32_t* a,
                                            const uint32_t* b) {
    asm volatile(
        "mma.sync.aligned.m16n8k8.row.col.f32.tf32.tf32.f32 "
        "{%0,%1,%2,%3}, {%4,%5,%6,%7}, {%8,%9}, {%0,%1,%2,%3};"
        : "+f"(c[0]), "+f"(c[1]), "+f"(c[2]), "+f"(c[3])
        : "r"(a[0]), "r"(a[1]), "r"(a[2]), "r"(a[3]),
          "r"(b[0]), "r"(b[1]));
}

// =====================================================================
// inc -> tf32-bits pre-convert (one-shot, ~5us)
// =====================================================================
__global__ void __launch_bounds__(256) conv_inc_kernel(const float* __restrict__ inc) {
    size_t i = ((size_t)blockIdx.x * 256 + threadIdx.x) * 4;
    float4 v = *reinterpret_cast<const float4*>(inc + i);
    uint4 o;
    o.x = f2tf32(v.x); o.y = f2tf32(v.y); o.z = f2tf32(v.z); o.w = f2tf32(v.w);
    *reinterpret_cast<uint4*>(g_incT + i) = o;
}

// =====================================================================
// Fused flux + GEMM kernel
//   out[b,s] = sum_r rate(b,r)*ab_pad[b,i0(r)]*ab_pad[b,i1(r)] * inc[s,r]
// CTA tile: M=64 (b), N=256 (all s), K-chunk TK=32 (r). 8 warps (warp 32x64).
// A tile (flux) computed in-kernel into smem (2 bufs); B tile cp.async (3 bufs).
// Pipeline groups (committed at iter k, AFTER the barrier): {B(k+2), P(k+3)}.
// wait_group 1 at iter k => group k complete => B(k) and P(k+1) ready.
// =====================================================================
static constexpr int TM = 64, TN = 256, TK = 32;
static constexpr int NK = R / TK;  // 256

static constexpr int A_STAGE = TM * TK * 4;          // 8192 (64 rows x 128B)
static constexpr int B_STAGE = TN * TK * 4;          // 32768 (256 rows x 128B)
static constexpr int P_STAGE = 768;                  // alpha/beta/gamma/rtype/rm
static constexpr int OFF_A = 0;
static constexpr int OFF_B = OFF_A + 2 * A_STAGE;    // 16384
static constexpr int OFF_P = OFF_B + 3 * B_STAGE;    // 114688
static constexpr int OFF_AB = OFF_P + 3 * P_STAGE;   // 116992
static constexpr int AB_PITCH = S + 1;               // 257 floats (odd: conflict-free gather)
static constexpr int OFF_AUX = OFF_AB + TM * AB_PITCH * 4;
static constexpr int SMEM_USED = OFF_AUX + 4 * TM * 4;
static constexpr int SMEM_TOTAL = SMEM_USED + 1024;  // alignment slack

__global__ void __launch_bounds__(256) fused_kernel(
    const float* __restrict__ ab, const float* __restrict__ temp,
    const float* __restrict__ cr, const float* __restrict__ fuv,
    const float* __restrict__ alpha, const float* __restrict__ beta,
    const float* __restrict__ gamma, const int* __restrict__ rm2,
    const int* __restrict__ rtype, float* __restrict__ out)
{
    extern __shared__ char smem_raw[];
    // Align to 1024 so SW128 tile bases are swizzle-correct
    const uint32_t sb_raw = smem_u32(smem_raw);
    const uint32_t sb = (sb_raw + 1023u) & ~1023u;
    char* smem = smem_raw + (sb - sb_raw);

    const int tid = threadIdx.x;
    const int wid = tid >> 5;
    const int lane = tid & 31;
    const int lr = lane >> 2;
    const int lc = lane & 3;
    const int m0 = blockIdx.x * TM;
    const int warp_m = wid & 1;
    const int warp_n = wid >> 1;

    float* s_ab  = reinterpret_cast<float*>(smem + OFF_AB);
    float* sL    = reinterpret_cast<float*>(smem + OFF_AUX);
    float* sInvT = sL + TM;
    float* sCr   = sL + 2 * TM;
    float* sFuv  = sL + 3 * TM;

    // ---------------- Prologue: abundances + per-b aux ----------------
    for (int i = tid; i < TM * S; i += 256) {
        int bi = i >> 8, si = i & 255;
        s_ab[bi * AB_PITCH + si] = ab[(size_t)(m0 + bi) * S + si];
    }
    if (tid < TM) {
        s_ab[tid * AB_PITCH + S] = 1.0f;  // ones column (index == S)
        float T = temp[m0 + tid];
        sL[tid] = __logf(T * (1.0f / 300.0f));
        sInvT[tid] = 1.0f / T;
        sCr[tid] = cr[m0 + tid];
        sFuv[tid] = fuv[m0 + tid];
    }

    // ---------------- Pipeline load lambdas ----------------
    auto load_B = [&](int kc) {
        const uint32_t base = sb + OFF_B + (kc % 3) * B_STAGE;
        const size_t k0 = (size_t)kc * TK;
#pragma unroll
        for (int q = 0; q < 8; q++) {
            int idx = q * 256 + tid;
            int row = idx >> 3, j = idx & 7;
            cp_async16(base + swz128((uint32_t)(row * 128 + j * 16)),
                       g_incT + (size_t)row * R + k0 + j * 4);
        }
    };
    auto load_P = [&](int kc) {
        const uint32_t pb = sb + OFF_P + (kc % 3) * P_STAGE;
        const int r0 = kc * TK;
        if (tid < 8)       cp_async16(pb + tid * 16, alpha + r0 + tid * 4);
        else if (tid < 16) cp_async16(pb + 128 + (tid - 8) * 16, beta + r0 + (tid - 8) * 4);
        else if (tid < 24) cp_async16(pb + 256 + (tid - 16) * 16, gamma + r0 + (tid - 16) * 4);
        else if (tid < 32) cp_async16(pb + 384 + (tid - 24) * 16, rtype + r0 + (tid - 24) * 4);
        else if (tid < 48) cp_async16(pb + 512 + (tid - 32) * 16, rm2 + 2 * r0 + (tid - 32) * 4);
    };

    // Flux producer: warp w computes r_local = 4w..4w+3 for all 64 b's.
    // rtype branch is warp-uniform; s_ab gather is conflict-free (pitch 257).
    auto flux_compute = [&](int kc) {
        const char* pb = smem + OFF_P + (kc % 3) * P_STAGE;
        const float* pA  = reinterpret_cast<const float*>(pb);
        const float* pBe = reinterpret_cast<const float*>(pb + 128);
        const float* pGa = reinterpret_cast<const float*>(pb + 256);
        const int*   pRt = reinterpret_cast<const int*>(pb + 384);
        const int2*  pRm = reinterpret_cast<const int2*>(pb + 512);
        const uint32_t an = sb + OFF_A + (kc & 1) * A_STAGE;
        const int b1 = lane, b2 = lane + 32;
        const float L1 = sL[b1], L2 = sL[b2];
        const float iT1 = sInvT[b1], iT2 = sInvT[b2];
        uint32_t v1[4], v2[4];
#pragma unroll
        for (int i = 0; i < 4; i++) {
            const int rl = wid * 4 + i;
            const float a_ = pA[rl], be = pBe[rl], ga = pGa[rl];
            const int rt = pRt[rl];
            const int2 ii = pRm[rl];
            float k1, k2;
            if (rt == 0) {
                k1 = a_ * __expf(be * L1 - ga * iT1);
                k2 = a_ * __expf(be * L2 - ga * iT2);
            } else if (rt == 1) {
                k1 = a_ * sCr[b1];
                k2 = a_ * sCr[b2];
            } else {
                const float e = a_ * __expf(-ga);
                k1 = e * sFuv[b1];
                k2 = e * sFuv[b2];
            }
            v1[i] = f2tf32(k1 * s_ab[b1 * AB_PITCH + ii.x] * s_ab[b1 * AB_PITCH + ii.y]);
            v2[i] = f2tf32(k2 * s_ab[b2 * AB_PITCH + ii.x] * s_ab[b2 * AB_PITCH + ii.y]);
        }
        sts128(an + swz128((uint32_t)(b1 * 128 + wid * 16)), v1[0], v1[1], v1[2], v1[3]);
        sts128(an + swz128((uint32_t)(b2 * 128 + wid * 16)), v2[0], v2[1], v2[2], v2[3]);
    };

    // ---------------- ldmatrix per-lane address constants ----------------
    const int ldsmRowA = ((lane >> 3) & 1) * 8 + (lane & 7);
    const int ldsmColA = (lane >> 4) * 16;
    const int ldsmRowB = (lane >> 4) * 8 + (lane & 7);
    const int ldsmColB = ((lane >> 3) & 1) * 16;

    float c[2][8][4];
#pragma unroll
    for (int i = 0; i < 2; i++)
#pragma unroll
        for (int j = 0; j < 8; j++)
#pragma unroll
            for (int q = 0; q < 4; q++) c[i][j][q] = 0.0f;

    // ---------------- Prologue pipeline ----------------
    // G0 = {B0, P0, P1}; G1 = {B1, P2}
    load_B(0); load_P(0); load_P(1); cp_commit();
    load_B(1); load_P(2); cp_commit();
    cp_wait1();        // G0 done: B0, P0, P1 ready
    __syncthreads();   // s_ab/aux visible
    flux_compute(0);   // A(0) -> abuf[0]  (needs P0)

    // ---------------- Main loop ----------------
    for (int k = 0; k < NK; k++) {
        cp_wait1();        // group k done => B(k), P(k+1) ready
        __syncthreads();   // A(k) + B(k) visible; all readers of bufs (k+2)%3 finished

        // Issue group k+2 = {B(k+2), P(k+3)} (safe: after the barrier)
        if (k + 2 < NK) load_B(k + 2);
        if (k + 3 < NK) load_P(k + 3);
        cp_commit();

        // MMA(k)
        const uint32_t abase = sb + OFF_A + (k & 1) * A_STAGE;
        const uint32_t bbase = sb + OFF_B + (k % 3) * B_STAGE;
#pragma unroll
        for (int ks = 0; ks < 4; ks++) {
            uint32_t a[2][4];
#pragma unroll
            for (int i = 0; i < 2; i++)
                ldsm_x4(a[i], abase + swz128((uint32_t)(
                    (warp_m * 32 + i * 16 + ldsmRowA) * 128 + ks * 32 + ldsmColA)));
            uint32_t bfr[4][4];
#pragma unroll
            for (int jj = 0; jj < 4; jj++)
                ldsm_x4(bfr[jj], bbase + swz128((uint32_t)(
                    (warp_n * 64 + jj * 16 + ldsmRowB) * 128 + ks * 32 + ldsmColB)));
#pragma unroll
            for (int i = 0; i < 2; i++)
#pragma unroll
                for (int jj = 0; jj < 4; jj++) {
                    mma_m16n8k8(c[i][2 * jj], a[i], &bfr[jj][0]);
                    mma_m16n8k8(c[i][2 * jj + 1], a[i], &bfr[jj][2]);
                }
        }

        // Produce A(k+1) into the other A buffer (needs P(k+1): ready)
        if (k + 1 < NK) flux_compute(k + 1);
    }

    // ---------------- Epilogue ----------------
#pragma unroll
    for (int i = 0; i < 2; i++) {
#pragma unroll
        for (int j = 0; j < 8; j++) {
            const int row = m0 + warp_m * 32 + i * 16 + lr;
            const int col = warp_n * 64 + j * 8 + 2 * lc;
            float2 v0; v0.x = c[i][j][0]; v0.y = c[i][j][1];
            float2 v1; v1.x = c[i][j][2]; v1.y = c[i][j][3];
            *reinterpret_cast<float2*>(out + (size_t)row * S + col) = v0;
            *reinterpret_cast<float2*>(out + (size_t)(row + 8) * S + col) = v1;
        }
    }
}

// =====================================================================
// Launch
// =====================================================================
extern "C" void kernel_launch(void* const* d_in, const int* in_sizes, int n_in,
                              void* d_out, int out_size) {
    // metadata order: time, abundances, temperature, cr_rate, fuv_rate,
    //                 incidence, alpha, beta, gamma, reactant_multipliers, rtype
    const float* ab    = (const float*)d_in[1];
    const float* temp  = (const float*)d_in[2];
    const float* cr    = (const float*)d_in[3];
    const float* fuv   = (const float*)d_in[4];
    const float* inc   = (const float*)d_in[5];
    const float* alpha = (const float*)d_in[6];
    const float* beta  = (const float*)d_in[7];
    const float* gamma = (const float*)d_in[8];
    const int*   rm    = (const int*)d_in[9];
    const int*   rtype = (const int*)d_in[10];
    float* out = (float*)d_out;

    cudaFuncSetAttribute(fused_kernel,
                         cudaFuncAttributeMaxDynamicSharedMemorySize, SMEM_TOTAL);

    conv_inc_kernel<<<(S * R) / (256 * 4), 256>>>(inc);
    fused_kernel<<<B / TM, 256, SMEM_TOTAL>>>(ab, temp, cr, fuv, alpha, beta,
                                              gamma, rm, rtype, out);
}